// round 7
// baseline (speedup 1.0000x reference)
#include <cuda_runtime.h>

// NormmaxBisect: alpha=1.5 normmax over last dim (d=2048).
// R5 finding: smem-resident row saturated l1tex (76%) -> DRAM stuck at 64%.
// R6: row back in REGISTERS but with TPB=256 (8 floats/thread = 2 float4),
// so regs fit ~32 -> launch_bounds(256,8) = full occupancy AND no full-row
// smem traffic. Only the ~13-element active set touches smem. __ldcs/st.cs
// keep the one-pass data out of L2. Newton(12) + dual shfl butterfly kept.

#define D       2048
#define TPB     256
#define V4      2      // float4 chunks per thread: D / (TPB*4) = 2
#define NW      (TPB / 32)
#define NEWTON  12

__device__ __forceinline__ float4 ldcs4(const float4* p) {
    float4 v;
    asm volatile("ld.global.cs.v4.f32 {%0,%1,%2,%3}, [%4];"
                 : "=f"(v.x), "=f"(v.y), "=f"(v.z), "=f"(v.w) : "l"(p));
    return v;
}
__device__ __forceinline__ void stcs4(float4* p, float4 v) {
    asm volatile("st.global.cs.v4.f32 [%0], {%1,%2,%3,%4};"
                 :: "l"(p), "f"(v.x), "f"(v.y), "f"(v.z), "f"(v.w) : "memory");
}

__global__ __launch_bounds__(TPB, 8)
void normmax_bisect_kernel(const float* __restrict__ X, float* __restrict__ Y) {
    __shared__ float s_act[D];       // compacted actives (typ ~13; worst D)
    __shared__ int   s_wsum[NW];
    __shared__ float s_wmax[NW];
    __shared__ float s_res[2];       // {tau, 1/sum}

    const size_t row = blockIdx.x;
    const float4* xr = reinterpret_cast<const float4*>(X + row * (size_t)D);
    float4*       yr = reinterpret_cast<float4*>(Y + row * (size_t)D);
    const int tid  = threadIdx.x;
    const int lane = tid & 31;
    const int wid  = tid >> 5;

    // ---- phase 1: load row into registers (coalesced), block max ----
    float4 v[V4];
    float mx = -3.402823466e38f;
#pragma unroll
    for (int k = 0; k < V4; k++) {
        v[k] = ldcs4(xr + k * TPB + tid);
        mx = fmaxf(mx, fmaxf(fmaxf(v[k].x, v[k].y), fmaxf(v[k].z, v[k].w)));
    }
#pragma unroll
    for (int o = 16; o; o >>= 1)
        mx = fmaxf(mx, __shfl_xor_sync(0xffffffffu, mx, o));
    if (lane == 0) s_wmax[wid] = mx;
    __syncthreads();
    mx = s_wmax[0];
#pragma unroll
    for (int w = 1; w < NW; w++) mx = fmaxf(mx, s_wmax[w]);

    const float thresh = mx - 1.0f;  // tau >= max-1 forever => x<=max-1 dead

    // ---- phase 2: ordered compaction of actives into smem ----
    int lcnt = 0;
#pragma unroll
    for (int k = 0; k < V4; k++) {
        lcnt += (v[k].x > thresh) + (v[k].y > thresh) +
                (v[k].z > thresh) + (v[k].w > thresh);
    }
    int scan = lcnt;
#pragma unroll
    for (int o = 1; o < 32; o <<= 1) {
        int n = __shfl_up_sync(0xffffffffu, scan, o);
        if (lane >= o) scan += n;
    }
    if (lane == 31) s_wsum[wid] = scan;
    __syncthreads();
    int base = scan - lcnt;
    int cnt  = 0;
#pragma unroll
    for (int w = 0; w < NW; w++) {
        if (w < wid) base += s_wsum[w];
        cnt += s_wsum[w];
    }
    {
        int p = base;
#pragma unroll
        for (int k = 0; k < V4; k++) {
            if (v[k].x > thresh) s_act[p++] = v[k].x;
            if (v[k].y > thresh) s_act[p++] = v[k].y;
            if (v[k].z > thresh) s_act[p++] = v[k].z;
            if (v[k].w > thresh) s_act[p++] = v[k].w;
        }
    }
    __syncthreads();

    // ---- phase 3: Newton on one warp (rotates across warp slots/SMSPs) ----
    // f(tau) = sum(max(x-tau,0)^3) - 1: convex, decreasing, f(max-1) >= 0
    // => monotone quadratic convergence from tau0 = max-1.
    if (wid == (int)(blockIdx.x & (NW - 1))) {
        float tau = mx - 1.0f;
        if (cnt <= 32) {                       // common case (~13 actives)
            float a = (lane < cnt) ? s_act[lane] : -3.402823466e38f;
#pragma unroll 1
            for (int it = 0; it < NEWTON; it++) {
                float t  = fmaxf(a - tau, 0.f);
                float t2 = t * t;
                float f2 = t2;
                float f3 = t2 * t;
#pragma unroll
                for (int o = 16; o; o >>= 1) {  // dual butterfly, pipelined
                    f3 += __shfl_xor_sync(0xffffffffu, f3, o);
                    f2 += __shfl_xor_sync(0xffffffffu, f2, o);
                }
                tau += (f3 - 1.0f) / (3.0f * f2);
            }
            float t = fmaxf(a - tau, 0.f);
            float s = t * t;
#pragma unroll
            for (int o = 16; o; o >>= 1)
                s += __shfl_xor_sync(0xffffffffu, s, o);
            if (lane == 0) { s_res[0] = tau; s_res[1] = 1.0f / s; }
        } else {                               // rare: stride smem actives
#pragma unroll 1
            for (int it = 0; it < NEWTON + 4; it++) {
                float f2 = 0.f, f3 = 0.f;
                for (int i = lane; i < cnt; i += 32) {
                    float t  = fmaxf(s_act[i] - tau, 0.f);
                    float t2 = t * t;
                    f2 += t2;
                    f3 = fmaf(t2, t, f3);
                }
#pragma unroll
                for (int o = 16; o; o >>= 1) {
                    f3 += __shfl_xor_sync(0xffffffffu, f3, o);
                    f2 += __shfl_xor_sync(0xffffffffu, f2, o);
                }
                tau += (f3 - 1.0f) / (3.0f * f2);
            }
            float f2 = 0.f;
            for (int i = lane; i < cnt; i += 32) {
                float t = fmaxf(s_act[i] - tau, 0.f);
                f2 = fmaf(t, t, f2);
            }
#pragma unroll
            for (int o = 16; o; o >>= 1)
                f2 += __shfl_xor_sync(0xffffffffu, f2, o);
            if (lane == 0) { s_res[0] = tau; s_res[1] = 1.0f / f2; }
        }
    }
    __syncthreads();

    // ---- phase 4: emit normalized p from register-held x (streaming) ----
    const float tau = s_res[0];
    const float inv = s_res[1];
#pragma unroll
    for (int k = 0; k < V4; k++) {
        float4 o;
        float u;
        u = fmaxf(v[k].x - tau, 0.f); o.x = u * u * inv;
        u = fmaxf(v[k].y - tau, 0.f); o.y = u * u * inv;
        u = fmaxf(v[k].z - tau, 0.f); o.z = u * u * inv;
        u = fmaxf(v[k].w - tau, 0.f); o.w = u * u * inv;
        stcs4(yr + k * TPB + tid, o);
    }
}

extern "C" void kernel_launch(void* const* d_in, const int* in_sizes, int n_in,
                              void* d_out, int out_size) {
    const float* X = (const float*)d_in[0];
    float*       Y = (float*)d_out;
    const int rows = in_sizes[0] / D;   // 65536
    normmax_bisect_kernel<<<rows, TPB>>>(X, Y);
}

// round 8
// speedup vs baseline: 1.6621x; 1.6621x over previous
#include <cuda_runtime.h>

// NormmaxBisect: alpha=1.5 normmax over last dim (d=2048).
// R6 (TPB=256) regressed: rows-in-flight per SM halved (8 vs 12-16), and that
// concurrency is what hides the per-row serial solve. Revert to R4 shape
// (TPB=128, register row, 12 blocks/SM) and cut the solve itself:
//  - warm start tau_b = max - cnt^(-1/3): provably f(tau_b) <= 0 (right of
//    root); Newton from the right of convex decreasing f lands left of the
//    root, then converges monotonically. Kills the 2/3-geometric crawl.
//  - uniform early exit on |sum(t^3)-1| < 2e-6 (sum(t^2) >= 1 provably, so
//    dtau <= ~7e-7), cap 20; typical rows take 3-6 iters vs fixed 12.
//  - on exit f2 = sum(t^2) at final tau -> inv = 1/f2, no epilogue reduction.

#define D       2048
#define TPB     128
#define V4      4      // float4 chunks per thread: D / (TPB*4) = 4
#define ITMAX   20

__device__ __forceinline__ void stcs4(float4* p, float4 v) {
    asm volatile("st.global.cs.v4.f32 [%0], {%1,%2,%3,%4};"
                 :: "l"(p), "f"(v.x), "f"(v.y), "f"(v.z), "f"(v.w) : "memory");
}

__global__ __launch_bounds__(TPB, 12)
void normmax_bisect_kernel(const float* __restrict__ X, float* __restrict__ Y) {
    __shared__ float s_act[D];          // compacted actives (typ ~13; worst D)
    __shared__ int   s_wsum[TPB / 32];
    __shared__ float s_wmax[TPB / 32];
    __shared__ float s_res[2];          // {tau, 1/sum}

    const size_t row = blockIdx.x;
    const float4* xr = reinterpret_cast<const float4*>(X + row * (size_t)D);
    float4*       yr = reinterpret_cast<float4*>(Y + row * (size_t)D);
    const int tid  = threadIdx.x;
    const int lane = tid & 31;
    const int wid  = tid >> 5;

    // ---- phase 1: load row into registers (coalesced float4), block max ----
    float4 v[V4];
    float mx = -3.402823466e38f;
#pragma unroll
    for (int k = 0; k < V4; k++) {
        v[k] = xr[k * TPB + tid];
        mx = fmaxf(mx, fmaxf(fmaxf(v[k].x, v[k].y), fmaxf(v[k].z, v[k].w)));
    }
#pragma unroll
    for (int o = 16; o; o >>= 1)
        mx = fmaxf(mx, __shfl_xor_sync(0xffffffffu, mx, o));
    if (lane == 0) s_wmax[wid] = mx;
    __syncthreads();
    mx = fmaxf(fmaxf(s_wmax[0], s_wmax[1]), fmaxf(s_wmax[2], s_wmax[3]));

    const float thresh = mx - 1.0f;  // tau >= max-1 forever => x<=max-1 dead

    // ---- phase 2: ordered compaction of actives into smem ----
    int lcnt = 0;
#pragma unroll
    for (int k = 0; k < V4; k++) {
        lcnt += (v[k].x > thresh) + (v[k].y > thresh) +
                (v[k].z > thresh) + (v[k].w > thresh);
    }
    int scan = lcnt;
#pragma unroll
    for (int o = 1; o < 32; o <<= 1) {
        int n = __shfl_up_sync(0xffffffffu, scan, o);
        if (lane >= o) scan += n;
    }
    if (lane == 31) s_wsum[wid] = scan;
    __syncthreads();
    int base = scan - lcnt;
#pragma unroll
    for (int w = 0; w < TPB / 32; w++)
        if (w < wid) base += s_wsum[w];
    const int cnt = s_wsum[0] + s_wsum[1] + s_wsum[2] + s_wsum[3];

    {
        int p = base;
#pragma unroll
        for (int k = 0; k < V4; k++) {
            if (v[k].x > thresh) s_act[p++] = v[k].x;
            if (v[k].y > thresh) s_act[p++] = v[k].y;
            if (v[k].z > thresh) s_act[p++] = v[k].z;
            if (v[k].w > thresh) s_act[p++] = v[k].w;
        }
    }
    __syncthreads();

    // ---- phase 3: warm-started Newton on one warp (rotates across SMSPs) --
    // f(tau) = sum(max(x-tau,0)^3) - 1: convex, decreasing.
    // tau_b = max - cnt^(-1/3) >= tau* (since cnt*t_max^3 >= sum t^3 = 1),
    // so f(tau_b) <= 0; Newton from the right lands left of the root (tangent
    // below convex f), then converges monotonically from the left.
    if (wid == (int)(blockIdx.x & 3)) {
        // t0 = cnt^(-1/3) via fast log2/exp2 (cnt >= 1 always: max is active)
        float t0  = __expf(-0.33333333f * __logf((float)cnt));
        float tau = mx - t0;
        const float tlo = mx - 1.0f;   // hard lower bound on tau*

        float f2, f3;
        if (cnt <= 32) {                       // common case (~13 actives)
            float a = (lane < cnt) ? s_act[lane] : -3.402823466e38f;
            int it = 0;
#pragma unroll 1
            for (;;) {
                float t  = fmaxf(a - tau, 0.f);
                float t2 = t * t;
                f2 = t2;
                f3 = t2 * t;
#pragma unroll
                for (int o = 16; o; o >>= 1) {  // dual butterfly, pipelined
                    f3 += __shfl_xor_sync(0xffffffffu, f3, o);
                    f2 += __shfl_xor_sync(0xffffffffu, f2, o);
                }
                if (fabsf(f3 - 1.0f) < 2e-6f || ++it >= ITMAX) break;
                tau = fmaxf(tau + (f3 - 1.0f) / (3.0f * f2), tlo);
            }
            if (lane == 0) { s_res[0] = tau; s_res[1] = 1.0f / f2; }
        } else {                               // rare: stride smem actives
            int it = 0;
#pragma unroll 1
            for (;;) {
                f2 = 0.f; f3 = 0.f;
                for (int i = lane; i < cnt; i += 32) {
                    float t  = fmaxf(s_act[i] - tau, 0.f);
                    float t2 = t * t;
                    f2 += t2;
                    f3 = fmaf(t2, t, f3);
                }
#pragma unroll
                for (int o = 16; o; o >>= 1) {
                    f3 += __shfl_xor_sync(0xffffffffu, f3, o);
                    f2 += __shfl_xor_sync(0xffffffffu, f2, o);
                }
                if (fabsf(f3 - 1.0f) < 2e-6f || ++it >= ITMAX + 8) break;
                tau = fmaxf(tau + (f3 - 1.0f) / (3.0f * f2), tlo);
            }
            if (lane == 0) { s_res[0] = tau; s_res[1] = 1.0f / f2; }
        }
    }
    __syncthreads();

    // ---- phase 4: emit normalized p from register-held x (streaming) ----
    const float tau = s_res[0];
    const float inv = s_res[1];
#pragma unroll
    for (int k = 0; k < V4; k++) {
        float4 o;
        float u;
        u = fmaxf(v[k].x - tau, 0.f); o.x = u * u * inv;
        u = fmaxf(v[k].y - tau, 0.f); o.y = u * u * inv;
        u = fmaxf(v[k].z - tau, 0.f); o.z = u * u * inv;
        u = fmaxf(v[k].w - tau, 0.f); o.w = u * u * inv;
        stcs4(yr + k * TPB + tid, o);
    }
}

extern "C" void kernel_launch(void* const* d_in, const int* in_sizes, int n_in,
                              void* d_out, int out_size) {
    const float* X = (const float*)d_in[0];
    float*       Y = (float*)d_out;
    const int rows = in_sizes[0] / D;   // 65536
    normmax_bisect_kernel<<<rows, TPB>>>(X, Y);
}

// round 9
// speedup vs baseline: 1.6704x; 1.0050x over previous
#include <cuda_runtime.h>

// NormmaxBisect: alpha=1.5 normmax over last dim (d=2048).
// R6 (TPB=256) regressed: rows-in-flight per SM halved (8 vs 12-16), and that
// concurrency is what hides the per-row serial solve. Revert to R4 shape
// (TPB=128, register row, 12 blocks/SM) and cut the solve itself:
//  - warm start tau_b = max - cnt^(-1/3): provably f(tau_b) <= 0 (right of
//    root); Newton from the right of convex decreasing f lands left of the
//    root, then converges monotonically. Kills the 2/3-geometric crawl.
//  - uniform early exit on |sum(t^3)-1| < 2e-6 (sum(t^2) >= 1 provably, so
//    dtau <= ~7e-7), cap 20; typical rows take 3-6 iters vs fixed 12.
//  - on exit f2 = sum(t^2) at final tau -> inv = 1/f2, no epilogue reduction.

#define D       2048
#define TPB     128
#define V4      4      // float4 chunks per thread: D / (TPB*4) = 4
#define ITMAX   20

__device__ __forceinline__ void stcs4(float4* p, float4 v) {
    asm volatile("st.global.cs.v4.f32 [%0], {%1,%2,%3,%4};"
                 :: "l"(p), "f"(v.x), "f"(v.y), "f"(v.z), "f"(v.w) : "memory");
}

__global__ __launch_bounds__(TPB, 12)
void normmax_bisect_kernel(const float* __restrict__ X, float* __restrict__ Y) {
    __shared__ float s_act[D];          // compacted actives (typ ~13; worst D)
    __shared__ int   s_wsum[TPB / 32];
    __shared__ float s_wmax[TPB / 32];
    __shared__ float s_res[2];          // {tau, 1/sum}

    const size_t row = blockIdx.x;
    const float4* xr = reinterpret_cast<const float4*>(X + row * (size_t)D);
    float4*       yr = reinterpret_cast<float4*>(Y + row * (size_t)D);
    const int tid  = threadIdx.x;
    const int lane = tid & 31;
    const int wid  = tid >> 5;

    // ---- phase 1: load row into registers (coalesced float4), block max ----
    float4 v[V4];
    float mx = -3.402823466e38f;
#pragma unroll
    for (int k = 0; k < V4; k++) {
        v[k] = xr[k * TPB + tid];
        mx = fmaxf(mx, fmaxf(fmaxf(v[k].x, v[k].y), fmaxf(v[k].z, v[k].w)));
    }
#pragma unroll
    for (int o = 16; o; o >>= 1)
        mx = fmaxf(mx, __shfl_xor_sync(0xffffffffu, mx, o));
    if (lane == 0) s_wmax[wid] = mx;
    __syncthreads();
    mx = fmaxf(fmaxf(s_wmax[0], s_wmax[1]), fmaxf(s_wmax[2], s_wmax[3]));

    const float thresh = mx - 1.0f;  // tau >= max-1 forever => x<=max-1 dead

    // ---- phase 2: ordered compaction of actives into smem ----
    int lcnt = 0;
#pragma unroll
    for (int k = 0; k < V4; k++) {
        lcnt += (v[k].x > thresh) + (v[k].y > thresh) +
                (v[k].z > thresh) + (v[k].w > thresh);
    }
    int scan = lcnt;
#pragma unroll
    for (int o = 1; o < 32; o <<= 1) {
        int n = __shfl_up_sync(0xffffffffu, scan, o);
        if (lane >= o) scan += n;
    }
    if (lane == 31) s_wsum[wid] = scan;
    __syncthreads();
    int base = scan - lcnt;
#pragma unroll
    for (int w = 0; w < TPB / 32; w++)
        if (w < wid) base += s_wsum[w];
    const int cnt = s_wsum[0] + s_wsum[1] + s_wsum[2] + s_wsum[3];

    {
        int p = base;
#pragma unroll
        for (int k = 0; k < V4; k++) {
            if (v[k].x > thresh) s_act[p++] = v[k].x;
            if (v[k].y > thresh) s_act[p++] = v[k].y;
            if (v[k].z > thresh) s_act[p++] = v[k].z;
            if (v[k].w > thresh) s_act[p++] = v[k].w;
        }
    }
    __syncthreads();

    // ---- phase 3: warm-started Newton on one warp (rotates across SMSPs) --
    // f(tau) = sum(max(x-tau,0)^3) - 1: convex, decreasing.
    // tau_b = max - cnt^(-1/3) >= tau* (since cnt*t_max^3 >= sum t^3 = 1),
    // so f(tau_b) <= 0; Newton from the right lands left of the root (tangent
    // below convex f), then converges monotonically from the left.
    if (wid == (int)(blockIdx.x & 3)) {
        // t0 = cnt^(-1/3) via fast log2/exp2 (cnt >= 1 always: max is active)
        float t0  = __expf(-0.33333333f * __logf((float)cnt));
        float tau = mx - t0;
        const float tlo = mx - 1.0f;   // hard lower bound on tau*

        float f2, f3;
        if (cnt <= 32) {                       // common case (~13 actives)
            float a = (lane < cnt) ? s_act[lane] : -3.402823466e38f;
            int it = 0;
#pragma unroll 1
            for (;;) {
                float t  = fmaxf(a - tau, 0.f);
                float t2 = t * t;
                f2 = t2;
                f3 = t2 * t;
#pragma unroll
                for (int o = 16; o; o >>= 1) {  // dual butterfly, pipelined
                    f3 += __shfl_xor_sync(0xffffffffu, f3, o);
                    f2 += __shfl_xor_sync(0xffffffffu, f2, o);
                }
                if (fabsf(f3 - 1.0f) < 2e-6f || ++it >= ITMAX) break;
                tau = fmaxf(tau + (f3 - 1.0f) / (3.0f * f2), tlo);
            }
            if (lane == 0) { s_res[0] = tau; s_res[1] = 1.0f / f2; }
        } else {                               // rare: stride smem actives
            int it = 0;
#pragma unroll 1
            for (;;) {
                f2 = 0.f; f3 = 0.f;
                for (int i = lane; i < cnt; i += 32) {
                    float t  = fmaxf(s_act[i] - tau, 0.f);
                    float t2 = t * t;
                    f2 += t2;
                    f3 = fmaf(t2, t, f3);
                }
#pragma unroll
                for (int o = 16; o; o >>= 1) {
                    f3 += __shfl_xor_sync(0xffffffffu, f3, o);
                    f2 += __shfl_xor_sync(0xffffffffu, f2, o);
                }
                if (fabsf(f3 - 1.0f) < 2e-6f || ++it >= ITMAX + 8) break;
                tau = fmaxf(tau + (f3 - 1.0f) / (3.0f * f2), tlo);
            }
            if (lane == 0) { s_res[0] = tau; s_res[1] = 1.0f / f2; }
        }
    }
    __syncthreads();

    // ---- phase 4: emit normalized p from register-held x (streaming) ----
    const float tau = s_res[0];
    const float inv = s_res[1];
#pragma unroll
    for (int k = 0; k < V4; k++) {
        float4 o;
        float u;
        u = fmaxf(v[k].x - tau, 0.f); o.x = u * u * inv;
        u = fmaxf(v[k].y - tau, 0.f); o.y = u * u * inv;
        u = fmaxf(v[k].z - tau, 0.f); o.z = u * u * inv;
        u = fmaxf(v[k].w - tau, 0.f); o.w = u * u * inv;
        stcs4(yr + k * TPB + tid, o);
    }
}

extern "C" void kernel_launch(void* const* d_in, const int* in_sizes, int n_in,
                              void* d_out, int out_size) {
    const float* X = (const float*)d_in[0];
    float*       Y = (float*)d_out;
    const int rows = in_sizes[0] / D;   // 65536
    normmax_bisect_kernel<<<rows, TPB>>>(X, Y);
}